// round 15
// baseline (speedup 1.0000x reference)
#include <cuda_runtime.h>
#include <cuda_fp16.h>
#include <math.h>
#include <stdint.h>

// Problem constants
constexpr int B_ = 2;
constexpr int S_ = 2048;
constexpr int D_ = 1024;
constexpr int H_ = 16;
constexpr int HD_ = 64;

constexpr size_t BSD  = (size_t)B_ * S_ * D_;          // 4,194,304
constexpr size_t BHSS = (size_t)B_ * H_ * S_ * S_;     // 134,217,728

// Scratch (device globals: allocation is forbidden)
__device__ __half g_QKVh[3 * BSD];         // Q | K | V
__device__ __half g_Ch[BSD];
__device__ __half g_Xh[BSD];               // fp16 x
__device__ __half g_Wh[4 * D_ * D_];       // fp16 Wq,Wk,Wv,Wo (contiguous)
__device__ float  g_attn_fallback[BHSS];

// ---------------------------------------------------------------------------
// Helpers
// ---------------------------------------------------------------------------
__device__ __forceinline__ uint32_t packh2(float a, float b) {
    __half2 h = __floats2half2_rn(a, b);
    return *reinterpret_cast<uint32_t*>(&h);
}
__device__ __forceinline__ float2 unpackh2(uint32_t u) {
    __half2 h = *reinterpret_cast<__half2*>(&u);
    return __half22float2(h);
}
__device__ __forceinline__ uint32_t h2exp2(uint32_t x) {
    uint32_t d;
    asm("ex2.approx.f16x2 %0, %1;" : "=r"(d) : "r"(x));
    return d;
}

__device__ __forceinline__ void hmma(float* c, const uint32_t* a, uint32_t b0, uint32_t b1) {
    asm volatile(
        "mma.sync.aligned.m16n8k16.row.col.f32.f16.f16.f32 "
        "{%0,%1,%2,%3},{%4,%5,%6,%7},{%8,%9},{%0,%1,%2,%3};"
        : "+f"(c[0]), "+f"(c[1]), "+f"(c[2]), "+f"(c[3])
        : "r"(a[0]), "r"(a[1]), "r"(a[2]), "r"(a[3]), "r"(b0), "r"(b1));
}

__device__ __forceinline__ void ldsm4(uint32_t* r, uint32_t addr) {
    asm volatile("ldmatrix.sync.aligned.m8n8.x4.shared.b16 {%0,%1,%2,%3}, [%4];"
                 : "=r"(r[0]), "=r"(r[1]), "=r"(r[2]), "=r"(r[3]) : "r"(addr));
}
__device__ __forceinline__ void ldsm4t(uint32_t& r0, uint32_t& r1, uint32_t& r2, uint32_t& r3,
                                       uint32_t addr) {
    asm volatile("ldmatrix.sync.aligned.m8n8.x4.trans.shared.b16 {%0,%1,%2,%3}, [%4];"
                 : "=r"(r0), "=r"(r1), "=r"(r2), "=r"(r3) : "r"(addr));
}

__device__ __forceinline__ void cp16(uint32_t saddr, const void* gaddr) {
    asm volatile("cp.async.cg.shared.global [%0], [%1], 16;" :: "r"(saddr), "l"(gaddr));
}
__device__ __forceinline__ void cp_commit() {
    asm volatile("cp.async.commit_group;");
}
template <int N>
__device__ __forceinline__ void cp_wait() {
    asm volatile("cp.async.wait_group %0;" :: "n"(N));
}

__device__ __forceinline__ uint32_t ld32h(const __half* p) {
    return *reinterpret_cast<const uint32_t*>(p);
}

constexpr uint32_t ONES_H2 = 0x3C003C00u;  // (1.0h, 1.0h)

// ---------------------------------------------------------------------------
// Single fp32 -> fp16 conversion kernel: x (seg 0, 4x larger) + 4 weights.
// Grid covers 2*WN float4 chunks: first WN/... laid out by explicit ranges.
// ---------------------------------------------------------------------------
__global__ void tohalf_all(const float4* __restrict__ x,
                           const float4* __restrict__ w0, const float4* __restrict__ w1,
                           const float4* __restrict__ w2, const float4* __restrict__ w3,
                           uint2* __restrict__ xh, uint2* __restrict__ wh,
                           int nx4, int nw4)
{
    int i = blockIdx.x * blockDim.x + threadIdx.x;
    if (i < nx4) {
        float4 v = x[i];
        xh[i] = make_uint2(packh2(v.x, v.y), packh2(v.z, v.w));
    }
    int j = i - nx4;
    if (j >= 0 && j < 4 * nw4) {
        int seg = j / nw4;
        int off = j - seg * nw4;
        const float4* src = (seg == 0) ? w0 : (seg == 1) ? w1 : (seg == 2) ? w2 : w3;
        float4 v = src[off];
        wh[j] = make_uint2(packh2(v.x, v.y), packh2(v.z, v.w));
    }
}

// ---------------------------------------------------------------------------
// fp16 NT GEMM with ldmatrix fragments (proven R6-R14 version).
// MODE 0: merged QKV projection (Q scaled by 0.125*log2e for exp2 domain).
// MODE 1: output projection (fp32 out).
// ---------------------------------------------------------------------------
template <int MODE>
__global__ __launch_bounds__(256, 2) void proj2(
    const __half* __restrict__ A, const __half* __restrict__ Bm,
    const float* __restrict__ b0, const float* __restrict__ b1,
    const float* __restrict__ b2, __half* __restrict__ outh,
    float* __restrict__ outf)
{
    constexpr int LD = 40;
    constexpr int AW = 128 * LD;
    constexpr int STAGE = 2 * AW;
    constexpr int NS = 4;
    extern __shared__ __half smh[];

    const int tid = threadIdx.x;
    const size_t bm = (size_t)blockIdx.y * 128;
    const size_t bn = (size_t)blockIdx.x * 128;
    constexpr int T = D_ / 32;

    auto issue = [&](int t, int s) {
        const int k0 = t * 32;
        __half* As = smh + s * STAGE;
        __half* Bs = As + AW;
#pragma unroll
        for (int i = 0; i < 2; i++) {
            int f = tid + 256 * i;
            int r = f >> 2;
            int c = (f & 3) * 8;
            cp16((uint32_t)__cvta_generic_to_shared(As + r * LD + c),
                 A + (bm + r) * (size_t)D_ + k0 + c);
            cp16((uint32_t)__cvta_generic_to_shared(Bs + r * LD + c),
                 Bm + (bn + r) * (size_t)D_ + k0 + c);
        }
    };

#pragma unroll
    for (int s = 0; s < NS - 1; s++) {
        issue(s, s);
        cp_commit();
    }

    const int warp = tid >> 5, lane = tid & 31;
    const int wm = (warp >> 1) * 32;
    const int wn = (warp & 1) * 64;
    const int grp = lane >> 2, qid = lane & 3;
    const int lr8 = lane & 7;
    const int am = (lane >> 3) & 1;
    const int ak = (lane >> 4) * 8;

    float acc[2][8][4];
#pragma unroll
    for (int i = 0; i < 2; i++)
#pragma unroll
        for (int j = 0; j < 8; j++)
#pragma unroll
            for (int r = 0; r < 4; r++) acc[i][j][r] = 0.f;

    for (int t = 0; t < T; t++) {
        cp_wait<NS - 2>();
        __syncthreads();
        const __half* As = smh + (t % NS) * STAGE;
        const __half* Bs = As + AW;

        // prefetch next stage before compute (stage freed at t-1)
        if (t + NS - 1 < T) issue(t + NS - 1, (t + NS - 1) % NS);
        cp_commit();

        uint32_t afr[2][2][4];
#pragma unroll
        for (int i = 0; i < 2; i++)
#pragma unroll
            for (int ks = 0; ks < 2; ks++)
                ldsm4(afr[i][ks],
                      (uint32_t)__cvta_generic_to_shared(
                          As + (wm + 16 * i + lr8 + am * 8) * LD + 16 * ks + ak));
#pragma unroll
        for (int j = 0; j < 8; j++) {
            uint32_t bfr[4];
            ldsm4(bfr, (uint32_t)__cvta_generic_to_shared(
                           Bs + (wn + 8 * j + lr8) * LD + (lane >> 3) * 8));
#pragma unroll
            for (int i = 0; i < 2; i++) {
                hmma(acc[i][j], afr[i][0], bfr[0], bfr[1]);
                hmma(acc[i][j], afr[i][1], bfr[2], bfr[3]);
            }
        }
    }

    int seg = 0;
    const float* bias = b0;
    float alpha = 1.f;
    size_t ncolbase = bn;
    if (MODE == 0) {
        seg = blockIdx.x >> 3;
        bias = (seg == 0) ? b0 : (seg == 1) ? b1 : b2;
        alpha = (seg == 0) ? 0.18033688011116027f : 1.f;  // 0.125*log2(e)
        ncolbase = bn - (size_t)seg * 1024;
    }

#pragma unroll
    for (int i = 0; i < 2; i++) {
#pragma unroll
        for (int j = 0; j < 8; j++) {
            size_t row = bm + wm + 16 * i + grp;
            size_t col = ncolbase + wn + 8 * j + 2 * qid;
            float bx = bias[col], by = bias[col + 1];
            float v0 = (acc[i][j][0] + bx) * alpha;
            float v1 = (acc[i][j][1] + by) * alpha;
            float v2 = (acc[i][j][2] + bx) * alpha;
            float v3 = (acc[i][j][3] + by) * alpha;
            if (MODE == 0) {
                __half* C = outh + (size_t)seg * BSD;
                *(uint32_t*)(C + row * (size_t)D_ + col) = packh2(v0, v1);
                *(uint32_t*)(C + (row + 8) * (size_t)D_ + col) = packh2(v2, v3);
            } else {
                *(float2*)(outf + row * (size_t)D_ + col) = make_float2(v0, v1);
                *(float2*)(outf + (row + 8) * (size_t)D_ + col) = make_float2(v2, v3);
            }
        }
    }
}

// ---------------------------------------------------------------------------
// Fused fp16 attention (R14) with issue-before-process prefetch in both passes.
// Pass A: 256-key K-only stages. Pass B: 128-key K+V stages; per jjp: S-mma +
// exp, then PV mma, then shuffle+STG.128 attn stores.
// ---------------------------------------------------------------------------
constexpr int LDK2 = 72;                 // halves (64 + 8 pad) = 144B stride
constexpr int KW = 128 * LDK2;           // 9216 halves per 128-key tile
constexpr int CW = 2 * KW;               // K+V combined stage (pass B)
constexpr int SM_ATT_BYTES = 3 * CW * 2; // 110592 B
constexpr int KTA = 256;                 // pass-A keys per tile
constexpr int NTA = S_ / KTA;            // 8
constexpr int AW2 = KTA * LDK2;          // 18432 halves per stage
constexpr int KT = 128;                  // pass-B keys per tile
constexpr int NT_TILES = S_ / KT;        // 16

__global__ __launch_bounds__(256, 2) void attn_h(
    const __half* __restrict__ Q, const __half* __restrict__ K,
    const __half* __restrict__ V, float* __restrict__ attn,
    __half* __restrict__ ctx)
{
    extern __shared__ __half smh[];
    __half* sT = smh;

    const int tid = threadIdx.x;
    const int warp = tid >> 5, lane = tid & 31;
    const int grp = lane >> 2, qid = lane & 3;
    const int wm = warp * 16;

    const int z = blockIdx.y;
    const int b = z >> 4, h = z & 15;
    const size_t rowbase = (size_t)blockIdx.x * 128;
    const __half* Qg = Q + (size_t)b * S_ * D_ + h * HD_ + rowbase * D_;
    const __half* Kg = K + (size_t)b * S_ * D_ + h * HD_;
    const __half* Vg = V + (size_t)b * S_ * D_ + h * HD_;
    float* attng = attn + (size_t)z * S_ * S_ + rowbase * S_;

    uint32_t qa[4][4];
    {
        const __half* q0 = Qg + (size_t)(wm + grp) * D_;
        const __half* q1 = Qg + (size_t)(wm + grp + 8) * D_;
#pragma unroll
        for (int ks = 0; ks < 4; ks++) {
            qa[ks][0] = ld32h(q0 + 16 * ks + 2 * qid);
            qa[ks][1] = ld32h(q1 + 16 * ks + 2 * qid);
            qa[ks][2] = ld32h(q0 + 16 * ks + 2 * qid + 8);
            qa[ks][3] = ld32h(q1 + 16 * ks + 2 * qid + 8);
        }
    }

    auto issueKA = [&](int t, int s) {
        __half* kd = sT + s * AW2;
        const __half* src = Kg + (size_t)t * KTA * D_;
#pragma unroll
        for (int i = 0; i < 8; i++) {
            int f = tid + 256 * i;
            int r = f >> 3;
            int c = (f & 7) * 8;
            cp16((uint32_t)__cvta_generic_to_shared(kd + r * LDK2 + c),
                 src + (size_t)r * D_ + c);
        }
    };
    auto issueK = [&](int t, int s) {
        __half* kd = sT + s * CW;
        const __half* src = Kg + (size_t)t * KT * D_;
#pragma unroll
        for (int i = 0; i < 4; i++) {
            int f = tid + 256 * i;
            int r = f >> 3;
            int c = (f & 7) * 8;
            cp16((uint32_t)__cvta_generic_to_shared(kd + r * LDK2 + c),
                 src + (size_t)r * D_ + c);
        }
    };
    auto issueV = [&](int t, int s) {
        __half* vd = sT + s * CW + KW;
        const __half* src = Vg + (size_t)t * KT * D_;
#pragma unroll
        for (int i = 0; i < 4; i++) {
            int f = tid + 256 * i;
            int r = f >> 3;
            int c = (f & 7) * 8;
            cp16((uint32_t)__cvta_generic_to_shared(vd + r * LDK2 + c),
                 src + (size_t)r * D_ + c);
        }
    };

    auto smma = [&](const __half* Ks, int jj, float* c) {
        c[0] = c[1] = c[2] = c[3] = 0.f;
        const __half* kp = Ks + (jj * 8 + (lane & 7)) * LDK2 + ((lane >> 3) * 8);
        uint32_t m[4];
        ldsm4(m, (uint32_t)__cvta_generic_to_shared(kp));
        hmma(c, qa[0], m[0], m[1]);
        hmma(c, qa[1], m[2], m[3]);
        ldsm4(m, (uint32_t)__cvta_generic_to_shared(kp + 32));
        hmma(c, qa[2], m[0], m[1]);
        hmma(c, qa[3], m[2], m[3]);
    };

    // ================= Pass A: rowsums of e = 2^S (8 big tiles) =============
    float rs[4] = {0.f, 0.f, 0.f, 0.f};

    issueKA(0, 0); cp_commit();
    issueKA(1, 1); cp_commit();
    for (int t = 0; t < NTA; t++) {
        cp_wait<1>();
        __syncthreads();
        const __half* Ks = sT + (t % 3) * AW2;

        // prefetch before compute (stage (t+2)%3 freed at t-1)
        if (t + 2 < NTA) issueKA(t + 2, (t + 2) % 3);
        cp_commit();

#pragma unroll
        for (int jjp = 0; jjp < 16; jjp++) {
            uint32_t pa[4];
#pragma unroll
            for (int hx = 0; hx < 2; hx++) {
                float c[4];
                smma(Ks, 2 * jjp + hx, c);
                pa[2 * hx + 0] = h2exp2(packh2(c[0], c[1]));
                pa[2 * hx + 1] = h2exp2(packh2(c[2], c[3]));
            }
            hmma(rs, pa, ONES_H2, ONES_H2);
        }
    }
    cp_wait<0>();
    __syncthreads();

    const float rinv0 = 1.f / rs[0];
    const float rinv1 = 1.f / rs[2];

    // ================= Pass B: PV mma first, attn stores after ==============
    float cacc[8][4];
#pragma unroll
    for (int t = 0; t < 8; t++)
#pragma unroll
        for (int r = 0; r < 4; r++) cacc[t][r] = 0.f;

    issueK(0, 0); issueV(0, 0); cp_commit();
    issueK(1, 1); issueV(1, 1); cp_commit();

    const int sbl = (lane & ~3) + 2 * (qid & 1);
    const bool hiHalf = (qid >= 2);

    for (int t = 0; t < NT_TILES; t++) {
        cp_wait<1>();
        __syncthreads();
        const __half* Ks = sT + (t % 3) * CW;
        const __half* Vs = Ks + KW;

        // prefetch before compute
        if (t + 2 < NT_TILES) { issueK(t + 2, (t + 2) % 3); issueV(t + 2, (t + 2) % 3); }
        cp_commit();

#pragma unroll
        for (int jjp = 0; jjp < 8; jjp++) {
            uint32_t pa[4];
#pragma unroll
            for (int hx = 0; hx < 2; hx++) {
                float c[4];
                smma(Ks, 2 * jjp + hx, c);
                pa[2 * hx + 0] = h2exp2(packh2(c[0], c[1]));  // row0 pair
                pa[2 * hx + 1] = h2exp2(packh2(c[2], c[3]));  // row1 pair
            }

            // PV first (keeps tensor pipe busy; stores depend only on pa)
            const int m = lane >> 3;
            const int keyr = 16 * jjp + (m & 1) * 8 + (lane & 7);
            const int dimo = (m >> 1) * 8;
#pragma unroll
            for (int nb = 0; nb < 4; nb++) {
                const __half* vp = Vs + keyr * LDK2 + nb * 16 + dimo;
                uint32_t r0, r1, r2, r3;
                ldsm4t(r0, r1, r2, r3, (uint32_t)__cvta_generic_to_shared(vp));
                hmma(cacc[2 * nb + 0], pa, r0, r1);
                hmma(cacc[2 * nb + 1], pa, r2, r3);
            }

            // attn stores: quad-shuffle regroup -> float4 per row
            {
                uint32_t a0 = __shfl_sync(0xffffffffu, pa[0], sbl);
                uint32_t a1 = __shfl_sync(0xffffffffu, pa[0], sbl + 1);
                uint32_t b0 = __shfl_sync(0xffffffffu, pa[2], sbl);
                uint32_t b1 = __shfl_sync(0xffffffffu, pa[2], sbl + 1);
                uint32_t u0 = hiHalf ? b0 : a0;
                uint32_t u1 = hiHalf ? b1 : a1;
                float2 f0 = unpackh2(u0), f1 = unpackh2(u1);
                const size_t col = (size_t)t * KT + jjp * 16 + 4 * qid;
                float4 o;
                o.x = f0.x * rinv0; o.y = f0.y * rinv0;
                o.z = f1.x * rinv0; o.w = f1.y * rinv0;
                __stcs((float4*)(attng + (size_t)(wm + grp) * S_ + col), o);

                a0 = __shfl_sync(0xffffffffu, pa[1], sbl);
                a1 = __shfl_sync(0xffffffffu, pa[1], sbl + 1);
                b0 = __shfl_sync(0xffffffffu, pa[3], sbl);
                b1 = __shfl_sync(0xffffffffu, pa[3], sbl + 1);
                u0 = hiHalf ? b0 : a0;
                u1 = hiHalf ? b1 : a1;
                f0 = unpackh2(u0); f1 = unpackh2(u1);
                o.x = f0.x * rinv1; o.y = f0.y * rinv1;
                o.z = f1.x * rinv1; o.w = f1.y * rinv1;
                __stcs((float4*)(attng + (size_t)(wm + grp + 8) * S_ + col), o);
            }
        }
    }

    __half* ctxg = ctx + (size_t)b * S_ * D_ + h * HD_ + rowbase * D_;
#pragma unroll
    for (int tt = 0; tt < 8; tt++) {
        const int col = 8 * tt + 2 * qid;
        *(uint32_t*)(ctxg + (size_t)(wm + grp) * D_ + col) =
            packh2(cacc[tt][0] * rinv0, cacc[tt][1] * rinv0);
        *(uint32_t*)(ctxg + (size_t)(wm + grp + 8) * D_ + col) =
            packh2(cacc[tt][2] * rinv1, cacc[tt][3] * rinv1);
    }
}

// ---------------------------------------------------------------------------
extern "C" void kernel_launch(void* const* d_in, const int* in_sizes, int n_in,
                              void* d_out, int out_size)
{
    const float* x  = (const float*)d_in[0];
    const float* Wq = (const float*)d_in[1];
    const float* bq = (const float*)d_in[2];
    const float* Wk = (const float*)d_in[3];
    const float* bk = (const float*)d_in[4];
    const float* Wv = (const float*)d_in[5];
    const float* bv = (const float*)d_in[6];
    const float* Wo = (const float*)d_in[7];
    const float* bo = (const float*)d_in[8];

    float* out = (float*)d_out;

    __half *QKV, *Cp, *Xp, *Wh;
    cudaGetSymbolAddress((void**)&QKV, g_QKVh);
    cudaGetSymbolAddress((void**)&Cp, g_Ch);
    cudaGetSymbolAddress((void**)&Xp, g_Xh);
    cudaGetSymbolAddress((void**)&Wh, g_Wh);

    float* attn;
    if ((size_t)out_size >= BSD + BHSS) {
        attn = out + BSD;
    } else {
        cudaGetSymbolAddress((void**)&attn, g_attn_fallback);
    }

    constexpr int WN = D_ * D_;
    constexpr int W4 = WN / 4;        // float4 per weight matrix
    constexpr int X4 = (int)(BSD / 4);

    // 0) convert x + all 4 weights in ONE launch
    tohalf_all<<<(X4 + 4 * W4 + 255) / 256, 256>>>(
        (const float4*)x, (const float4*)Wq, (const float4*)Wk,
        (const float4*)Wv, (const float4*)Wo,
        (uint2*)Xp, (uint2*)Wh, X4, W4);

    constexpr int SMEM_P = 4 * (2 * 128 * 40) * 2;  // 81920 B
    cudaFuncSetAttribute(proj2<0>, cudaFuncAttributeMaxDynamicSharedMemorySize, SMEM_P);
    cudaFuncSetAttribute(proj2<1>, cudaFuncAttributeMaxDynamicSharedMemorySize, SMEM_P);
    cudaFuncSetAttribute(attn_h, cudaFuncAttributeMaxDynamicSharedMemorySize, SM_ATT_BYTES);

    // 1) merged QKV projection (Q in exp2 domain)
    dim3 gqkv(3 * D_ / 128, (B_ * S_) / 128);  // (24, 32)
    proj2<0><<<gqkv, 256, SMEM_P>>>(Xp, Wh, bq, bk, bv, QKV, nullptr);

    // 2) fused attention
    dim3 gatt(S_ / 128, B_ * H_);  // (16, 32)
    attn_h<<<gatt, 256, SM_ATT_BYTES>>>(QKV, QKV + BSD, QKV + 2 * BSD, attn, Cp);

    // 3) out = ctx @ Wo^T + bo (fp32 output)
    dim3 gout(D_ / 128, (B_ * S_) / 128);  // (8, 32)
    proj2<1><<<gout, 256, SMEM_P>>>(Cp, Wh + 3 * WN, bo, nullptr, nullptr, nullptr, out);
}

// round 16
// speedup vs baseline: 1.0561x; 1.0561x over previous
#include <cuda_runtime.h>
#include <cuda_fp16.h>
#include <math.h>
#include <stdint.h>

// Problem constants
constexpr int B_ = 2;
constexpr int S_ = 2048;
constexpr int D_ = 1024;
constexpr int H_ = 16;
constexpr int HD_ = 64;

constexpr size_t BSD  = (size_t)B_ * S_ * D_;          // 4,194,304
constexpr size_t BHSS = (size_t)B_ * H_ * S_ * S_;     // 134,217,728

// Scratch (device globals: allocation is forbidden)
__device__ __half g_QKVh[3 * BSD];         // Q | K | V
__device__ __half g_Ch[BSD];
__device__ __half g_Xh[BSD];               // fp16 x
__device__ __half g_Wh[4 * D_ * D_];       // fp16 Wq,Wk,Wv,Wo (contiguous)
__device__ float  g_attn_fallback[BHSS];

// ---------------------------------------------------------------------------
// Helpers
// ---------------------------------------------------------------------------
__device__ __forceinline__ uint32_t packh2(float a, float b) {
    __half2 h = __floats2half2_rn(a, b);
    return *reinterpret_cast<uint32_t*>(&h);
}
__device__ __forceinline__ float2 unpackh2(uint32_t u) {
    __half2 h = *reinterpret_cast<__half2*>(&u);
    return __half22float2(h);
}
__device__ __forceinline__ uint32_t h2exp2(uint32_t x) {
    uint32_t d;
    asm("ex2.approx.f16x2 %0, %1;" : "=r"(d) : "r"(x));
    return d;
}

__device__ __forceinline__ void hmma(float* c, const uint32_t* a, uint32_t b0, uint32_t b1) {
    asm volatile(
        "mma.sync.aligned.m16n8k16.row.col.f32.f16.f16.f32 "
        "{%0,%1,%2,%3},{%4,%5,%6,%7},{%8,%9},{%0,%1,%2,%3};"
        : "+f"(c[0]), "+f"(c[1]), "+f"(c[2]), "+f"(c[3])
        : "r"(a[0]), "r"(a[1]), "r"(a[2]), "r"(a[3]), "r"(b0), "r"(b1));
}

__device__ __forceinline__ void ldsm4(uint32_t* r, uint32_t addr) {
    asm volatile("ldmatrix.sync.aligned.m8n8.x4.shared.b16 {%0,%1,%2,%3}, [%4];"
                 : "=r"(r[0]), "=r"(r[1]), "=r"(r[2]), "=r"(r[3]) : "r"(addr));
}
__device__ __forceinline__ void ldsm4t(uint32_t& r0, uint32_t& r1, uint32_t& r2, uint32_t& r3,
                                       uint32_t addr) {
    asm volatile("ldmatrix.sync.aligned.m8n8.x4.trans.shared.b16 {%0,%1,%2,%3}, [%4];"
                 : "=r"(r0), "=r"(r1), "=r"(r2), "=r"(r3) : "r"(addr));
}

__device__ __forceinline__ void cp16(uint32_t saddr, const void* gaddr) {
    asm volatile("cp.async.cg.shared.global [%0], [%1], 16;" :: "r"(saddr), "l"(gaddr));
}
__device__ __forceinline__ void cp_commit() {
    asm volatile("cp.async.commit_group;");
}
template <int N>
__device__ __forceinline__ void cp_wait() {
    asm volatile("cp.async.wait_group %0;" :: "n"(N));
}

__device__ __forceinline__ uint32_t ld32h(const __half* p) {
    return *reinterpret_cast<const uint32_t*>(p);
}

constexpr uint32_t ONES_H2 = 0x3C003C00u;  // (1.0h, 1.0h)

// ---------------------------------------------------------------------------
// Single fp32 -> fp16 conversion kernel: x + 4 weight matrices, one launch.
// ---------------------------------------------------------------------------
__global__ void tohalf_all(const float4* __restrict__ x,
                           const float4* __restrict__ w0, const float4* __restrict__ w1,
                           const float4* __restrict__ w2, const float4* __restrict__ w3,
                           uint2* __restrict__ xh, uint2* __restrict__ wh,
                           int nx4, int nw4)
{
    int i = blockIdx.x * blockDim.x + threadIdx.x;
    if (i < nx4) {
        float4 v = x[i];
        xh[i] = make_uint2(packh2(v.x, v.y), packh2(v.z, v.w));
    }
    int j = i - nx4;
    if (j >= 0 && j < 4 * nw4) {
        int seg = j / nw4;
        int off = j - seg * nw4;
        const float4* src = (seg == 0) ? w0 : (seg == 1) ? w1 : (seg == 2) ? w2 : w3;
        float4 v = src[off];
        wh[j] = make_uint2(packh2(v.x, v.y), packh2(v.z, v.w));
    }
}

// ---------------------------------------------------------------------------
// fp16 NT GEMM with ldmatrix fragments (R14 version: issue AFTER compute).
// MODE 0: merged QKV projection (Q scaled by 0.125*log2e for exp2 domain).
// MODE 1: output projection (fp32 out).
// ---------------------------------------------------------------------------
template <int MODE>
__global__ __launch_bounds__(256, 2) void proj2(
    const __half* __restrict__ A, const __half* __restrict__ Bm,
    const float* __restrict__ b0, const float* __restrict__ b1,
    const float* __restrict__ b2, __half* __restrict__ outh,
    float* __restrict__ outf)
{
    constexpr int LD = 40;
    constexpr int AW = 128 * LD;
    constexpr int STAGE = 2 * AW;
    constexpr int NS = 4;
    extern __shared__ __half smh[];

    const int tid = threadIdx.x;
    const size_t bm = (size_t)blockIdx.y * 128;
    const size_t bn = (size_t)blockIdx.x * 128;
    constexpr int T = D_ / 32;

    auto issue = [&](int t, int s) {
        const int k0 = t * 32;
        __half* As = smh + s * STAGE;
        __half* Bs = As + AW;
#pragma unroll
        for (int i = 0; i < 2; i++) {
            int f = tid + 256 * i;
            int r = f >> 2;
            int c = (f & 3) * 8;
            cp16((uint32_t)__cvta_generic_to_shared(As + r * LD + c),
                 A + (bm + r) * (size_t)D_ + k0 + c);
            cp16((uint32_t)__cvta_generic_to_shared(Bs + r * LD + c),
                 Bm + (bn + r) * (size_t)D_ + k0 + c);
        }
    };

#pragma unroll
    for (int s = 0; s < NS - 1; s++) {
        issue(s, s);
        cp_commit();
    }

    const int warp = tid >> 5, lane = tid & 31;
    const int wm = (warp >> 1) * 32;
    const int wn = (warp & 1) * 64;
    const int grp = lane >> 2, qid = lane & 3;
    const int lr8 = lane & 7;
    const int am = (lane >> 3) & 1;
    const int ak = (lane >> 4) * 8;

    float acc[2][8][4];
#pragma unroll
    for (int i = 0; i < 2; i++)
#pragma unroll
        for (int j = 0; j < 8; j++)
#pragma unroll
            for (int r = 0; r < 4; r++) acc[i][j][r] = 0.f;

    for (int t = 0; t < T; t++) {
        cp_wait<NS - 2>();
        __syncthreads();
        const __half* As = smh + (t % NS) * STAGE;
        const __half* Bs = As + AW;

        uint32_t afr[2][2][4];
#pragma unroll
        for (int i = 0; i < 2; i++)
#pragma unroll
            for (int ks = 0; ks < 2; ks++)
                ldsm4(afr[i][ks],
                      (uint32_t)__cvta_generic_to_shared(
                          As + (wm + 16 * i + lr8 + am * 8) * LD + 16 * ks + ak));
#pragma unroll
        for (int j = 0; j < 8; j++) {
            uint32_t bfr[4];
            ldsm4(bfr, (uint32_t)__cvta_generic_to_shared(
                           Bs + (wn + 8 * j + lr8) * LD + (lane >> 3) * 8));
#pragma unroll
            for (int i = 0; i < 2; i++) {
                hmma(acc[i][j], afr[i][0], bfr[0], bfr[1]);
                hmma(acc[i][j], afr[i][1], bfr[2], bfr[3]);
            }
        }

        if (t + NS - 1 < T) issue(t + NS - 1, (t + NS - 1) % NS);
        cp_commit();
    }

    int seg = 0;
    const float* bias = b0;
    float alpha = 1.f;
    size_t ncolbase = bn;
    if (MODE == 0) {
        seg = blockIdx.x >> 3;
        bias = (seg == 0) ? b0 : (seg == 1) ? b1 : b2;
        alpha = (seg == 0) ? 0.18033688011116027f : 1.f;  // 0.125*log2(e)
        ncolbase = bn - (size_t)seg * 1024;
    }

#pragma unroll
    for (int i = 0; i < 2; i++) {
#pragma unroll
        for (int j = 0; j < 8; j++) {
            size_t row = bm + wm + 16 * i + grp;
            size_t col = ncolbase + wn + 8 * j + 2 * qid;
            float bx = bias[col], by = bias[col + 1];
            float v0 = (acc[i][j][0] + bx) * alpha;
            float v1 = (acc[i][j][1] + by) * alpha;
            float v2 = (acc[i][j][2] + bx) * alpha;
            float v3 = (acc[i][j][3] + by) * alpha;
            if (MODE == 0) {
                __half* C = outh + (size_t)seg * BSD;
                *(uint32_t*)(C + row * (size_t)D_ + col) = packh2(v0, v1);
                *(uint32_t*)(C + (row + 8) * (size_t)D_ + col) = packh2(v2, v3);
            } else {
                *(float2*)(outf + row * (size_t)D_ + col) = make_float2(v0, v1);
                *(float2*)(outf + (row + 8) * (size_t)D_ + col) = make_float2(v2, v3);
            }
        }
    }
}

// ---------------------------------------------------------------------------
// Fused fp16 attention (R14 exactly: issue AFTER compute in both passes).
// Pass A: 256-key K-only stages -> half the barriers.
// Pass B: 128-key K+V stages; per jjp: S-mma + exp, then PV mma, then
// shuffle+STG.128 attn stores.
// ---------------------------------------------------------------------------
constexpr int LDK2 = 72;                 // halves (64 + 8 pad) = 144B stride
constexpr int KW = 128 * LDK2;           // 9216 halves per 128-key tile
constexpr int CW = 2 * KW;               // K+V combined stage (pass B)
constexpr int SM_ATT_BYTES = 3 * CW * 2; // 110592 B
constexpr int KTA = 256;                 // pass-A keys per tile
constexpr int NTA = S_ / KTA;            // 8
constexpr int AW2 = KTA * LDK2;          // 18432 halves per stage
constexpr int KT = 128;                  // pass-B keys per tile
constexpr int NT_TILES = S_ / KT;        // 16

__global__ __launch_bounds__(256, 2) void attn_h(
    const __half* __restrict__ Q, const __half* __restrict__ K,
    const __half* __restrict__ V, float* __restrict__ attn,
    __half* __restrict__ ctx)
{
    extern __shared__ __half smh[];
    __half* sT = smh;

    const int tid = threadIdx.x;
    const int warp = tid >> 5, lane = tid & 31;
    const int grp = lane >> 2, qid = lane & 3;
    const int wm = warp * 16;

    const int z = blockIdx.y;
    const int b = z >> 4, h = z & 15;
    const size_t rowbase = (size_t)blockIdx.x * 128;
    const __half* Qg = Q + (size_t)b * S_ * D_ + h * HD_ + rowbase * D_;
    const __half* Kg = K + (size_t)b * S_ * D_ + h * HD_;
    const __half* Vg = V + (size_t)b * S_ * D_ + h * HD_;
    float* attng = attn + (size_t)z * S_ * S_ + rowbase * S_;

    uint32_t qa[4][4];
    {
        const __half* q0 = Qg + (size_t)(wm + grp) * D_;
        const __half* q1 = Qg + (size_t)(wm + grp + 8) * D_;
#pragma unroll
        for (int ks = 0; ks < 4; ks++) {
            qa[ks][0] = ld32h(q0 + 16 * ks + 2 * qid);
            qa[ks][1] = ld32h(q1 + 16 * ks + 2 * qid);
            qa[ks][2] = ld32h(q0 + 16 * ks + 2 * qid + 8);
            qa[ks][3] = ld32h(q1 + 16 * ks + 2 * qid + 8);
        }
    }

    auto issueKA = [&](int t, int s) {
        __half* kd = sT + s * AW2;
        const __half* src = Kg + (size_t)t * KTA * D_;
#pragma unroll
        for (int i = 0; i < 8; i++) {
            int f = tid + 256 * i;
            int r = f >> 3;
            int c = (f & 7) * 8;
            cp16((uint32_t)__cvta_generic_to_shared(kd + r * LDK2 + c),
                 src + (size_t)r * D_ + c);
        }
    };
    auto issueK = [&](int t, int s) {
        __half* kd = sT + s * CW;
        const __half* src = Kg + (size_t)t * KT * D_;
#pragma unroll
        for (int i = 0; i < 4; i++) {
            int f = tid + 256 * i;
            int r = f >> 3;
            int c = (f & 7) * 8;
            cp16((uint32_t)__cvta_generic_to_shared(kd + r * LDK2 + c),
                 src + (size_t)r * D_ + c);
        }
    };
    auto issueV = [&](int t, int s) {
        __half* vd = sT + s * CW + KW;
        const __half* src = Vg + (size_t)t * KT * D_;
#pragma unroll
        for (int i = 0; i < 4; i++) {
            int f = tid + 256 * i;
            int r = f >> 3;
            int c = (f & 7) * 8;
            cp16((uint32_t)__cvta_generic_to_shared(vd + r * LDK2 + c),
                 src + (size_t)r * D_ + c);
        }
    };

    auto smma = [&](const __half* Ks, int jj, float* c) {
        c[0] = c[1] = c[2] = c[3] = 0.f;
        const __half* kp = Ks + (jj * 8 + (lane & 7)) * LDK2 + ((lane >> 3) * 8);
        uint32_t m[4];
        ldsm4(m, (uint32_t)__cvta_generic_to_shared(kp));
        hmma(c, qa[0], m[0], m[1]);
        hmma(c, qa[1], m[2], m[3]);
        ldsm4(m, (uint32_t)__cvta_generic_to_shared(kp + 32));
        hmma(c, qa[2], m[0], m[1]);
        hmma(c, qa[3], m[2], m[3]);
    };

    // ================= Pass A: rowsums of e = 2^S (8 big tiles) =============
    float rs[4] = {0.f, 0.f, 0.f, 0.f};

    issueKA(0, 0); cp_commit();
    issueKA(1, 1); cp_commit();
    for (int t = 0; t < NTA; t++) {
        cp_wait<1>();
        __syncthreads();
        const __half* Ks = sT + (t % 3) * AW2;
#pragma unroll
        for (int jjp = 0; jjp < 16; jjp++) {
            uint32_t pa[4];
#pragma unroll
            for (int hx = 0; hx < 2; hx++) {
                float c[4];
                smma(Ks, 2 * jjp + hx, c);
                pa[2 * hx + 0] = h2exp2(packh2(c[0], c[1]));
                pa[2 * hx + 1] = h2exp2(packh2(c[2], c[3]));
            }
            hmma(rs, pa, ONES_H2, ONES_H2);
        }
        if (t + 2 < NTA) issueKA(t + 2, (t + 2) % 3);
        cp_commit();
    }
    cp_wait<0>();
    __syncthreads();

    const float rinv0 = 1.f / rs[0];
    const float rinv1 = 1.f / rs[2];

    // ================= Pass B: PV mma first, attn stores after ==============
    float cacc[8][4];
#pragma unroll
    for (int t = 0; t < 8; t++)
#pragma unroll
        for (int r = 0; r < 4; r++) cacc[t][r] = 0.f;

    issueK(0, 0); issueV(0, 0); cp_commit();
    issueK(1, 1); issueV(1, 1); cp_commit();

    const int sbl = (lane & ~3) + 2 * (qid & 1);
    const bool hiHalf = (qid >= 2);

    for (int t = 0; t < NT_TILES; t++) {
        cp_wait<1>();
        __syncthreads();
        const __half* Ks = sT + (t % 3) * CW;
        const __half* Vs = Ks + KW;

#pragma unroll
        for (int jjp = 0; jjp < 8; jjp++) {
            uint32_t pa[4];
#pragma unroll
            for (int hx = 0; hx < 2; hx++) {
                float c[4];
                smma(Ks, 2 * jjp + hx, c);
                pa[2 * hx + 0] = h2exp2(packh2(c[0], c[1]));  // row0 pair
                pa[2 * hx + 1] = h2exp2(packh2(c[2], c[3]));  // row1 pair
            }

            // PV first (keeps tensor pipe busy; stores depend only on pa)
            const int m = lane >> 3;
            const int keyr = 16 * jjp + (m & 1) * 8 + (lane & 7);
            const int dimo = (m >> 1) * 8;
#pragma unroll
            for (int nb = 0; nb < 4; nb++) {
                const __half* vp = Vs + keyr * LDK2 + nb * 16 + dimo;
                uint32_t r0, r1, r2, r3;
                ldsm4t(r0, r1, r2, r3, (uint32_t)__cvta_generic_to_shared(vp));
                hmma(cacc[2 * nb + 0], pa, r0, r1);
                hmma(cacc[2 * nb + 1], pa, r2, r3);
            }

            // attn stores: quad-shuffle regroup -> float4 per row
            {
                uint32_t a0 = __shfl_sync(0xffffffffu, pa[0], sbl);
                uint32_t a1 = __shfl_sync(0xffffffffu, pa[0], sbl + 1);
                uint32_t b0 = __shfl_sync(0xffffffffu, pa[2], sbl);
                uint32_t b1 = __shfl_sync(0xffffffffu, pa[2], sbl + 1);
                uint32_t u0 = hiHalf ? b0 : a0;
                uint32_t u1 = hiHalf ? b1 : a1;
                float2 f0 = unpackh2(u0), f1 = unpackh2(u1);
                const size_t col = (size_t)t * KT + jjp * 16 + 4 * qid;
                float4 o;
                o.x = f0.x * rinv0; o.y = f0.y * rinv0;
                o.z = f1.x * rinv0; o.w = f1.y * rinv0;
                __stcs((float4*)(attng + (size_t)(wm + grp) * S_ + col), o);

                a0 = __shfl_sync(0xffffffffu, pa[1], sbl);
                a1 = __shfl_sync(0xffffffffu, pa[1], sbl + 1);
                b0 = __shfl_sync(0xffffffffu, pa[3], sbl);
                b1 = __shfl_sync(0xffffffffu, pa[3], sbl + 1);
                u0 = hiHalf ? b0 : a0;
                u1 = hiHalf ? b1 : a1;
                f0 = unpackh2(u0); f1 = unpackh2(u1);
                o.x = f0.x * rinv1; o.y = f0.y * rinv1;
                o.z = f1.x * rinv1; o.w = f1.y * rinv1;
                __stcs((float4*)(attng + (size_t)(wm + grp + 8) * S_ + col), o);
            }
        }
        if (t + 2 < NT_TILES) { issueK(t + 2, (t + 2) % 3); issueV(t + 2, (t + 2) % 3); }
        cp_commit();
    }

    __half* ctxg = ctx + (size_t)b * S_ * D_ + h * HD_ + rowbase * D_;
#pragma unroll
    for (int tt = 0; tt < 8; tt++) {
        const int col = 8 * tt + 2 * qid;
        *(uint32_t*)(ctxg + (size_t)(wm + grp) * D_ + col) =
            packh2(cacc[tt][0] * rinv0, cacc[tt][1] * rinv0);
        *(uint32_t*)(ctxg + (size_t)(wm + grp + 8) * D_ + col) =
            packh2(cacc[tt][2] * rinv1, cacc[tt][3] * rinv1);
    }
}

// ---------------------------------------------------------------------------
extern "C" void kernel_launch(void* const* d_in, const int* in_sizes, int n_in,
                              void* d_out, int out_size)
{
    const float* x  = (const float*)d_in[0];
    const float* Wq = (const float*)d_in[1];
    const float* bq = (const float*)d_in[2];
    const float* Wk = (const float*)d_in[3];
    const float* bk = (const float*)d_in[4];
    const float* Wv = (const float*)d_in[5];
    const float* bv = (const float*)d_in[6];
    const float* Wo = (const float*)d_in[7];
    const float* bo = (const float*)d_in[8];

    float* out = (float*)d_out;

    __half *QKV, *Cp, *Xp, *Wh;
    cudaGetSymbolAddress((void**)&QKV, g_QKVh);
    cudaGetSymbolAddress((void**)&Cp, g_Ch);
    cudaGetSymbolAddress((void**)&Xp, g_Xh);
    cudaGetSymbolAddress((void**)&Wh, g_Wh);

    float* attn;
    if ((size_t)out_size >= BSD + BHSS) {
        attn = out + BSD;
    } else {
        cudaGetSymbolAddress((void**)&attn, g_attn_fallback);
    }

    constexpr int WN = D_ * D_;
    constexpr int W4 = WN / 4;        // float4 per weight matrix
    constexpr int X4 = (int)(BSD / 4);

    // 0) convert x + all 4 weights in ONE launch
    tohalf_all<<<(X4 + 4 * W4 + 255) / 256, 256>>>(
        (const float4*)x, (const float4*)Wq, (const float4*)Wk,
        (const float4*)Wv, (const float4*)Wo,
        (uint2*)Xp, (uint2*)Wh, X4, W4);

    constexpr int SMEM_P = 4 * (2 * 128 * 40) * 2;  // 81920 B
    cudaFuncSetAttribute(proj2<0>, cudaFuncAttributeMaxDynamicSharedMemorySize, SMEM_P);
    cudaFuncSetAttribute(proj2<1>, cudaFuncAttributeMaxDynamicSharedMemorySize, SMEM_P);
    cudaFuncSetAttribute(attn_h, cudaFuncAttributeMaxDynamicSharedMemorySize, SM_ATT_BYTES);

    // 1) merged QKV projection (Q in exp2 domain)
    dim3 gqkv(3 * D_ / 128, (B_ * S_) / 128);  // (24, 32)
    proj2<0><<<gqkv, 256, SMEM_P>>>(Xp, Wh, bq, bk, bv, QKV, nullptr);

    // 2) fused attention
    dim3 gatt(S_ / 128, B_ * H_);  // (16, 32)
    attn_h<<<gatt, 256, SM_ATT_BYTES>>>(QKV, QKV + BSD, QKV + 2 * BSD, attn, Cp);

    // 3) out = ctx @ Wo^T + bo (fp32 output)
    dim3 gout(D_ / 128, (B_ * S_) / 128);  // (8, 32)
    proj2<1><<<gout, 256, SMEM_P>>>(Cp, Wh + 3 * WN, bo, nullptr, nullptr, nullptr, out);
}

// round 17
// speedup vs baseline: 1.0681x; 1.0114x over previous
#include <cuda_runtime.h>
#include <cuda_fp16.h>
#include <math.h>
#include <stdint.h>

// Problem constants
constexpr int B_ = 2;
constexpr int S_ = 2048;
constexpr int D_ = 1024;
constexpr int H_ = 16;
constexpr int HD_ = 64;

constexpr size_t BSD  = (size_t)B_ * S_ * D_;          // 4,194,304
constexpr size_t BHSS = (size_t)B_ * H_ * S_ * S_;     // 134,217,728

// Scratch (device globals: allocation is forbidden)
__device__ __half g_QKVh[3 * BSD];         // Q | K | V
__device__ __half g_Ch[BSD];
__device__ __half g_Xh[BSD];               // fp16 x
__device__ __half g_Wh[4 * D_ * D_];       // fp16 Wq,Wk,Wv,Wo (contiguous)
__device__ float  g_attn_fallback[BHSS];

// ---------------------------------------------------------------------------
// Helpers
// ---------------------------------------------------------------------------
__device__ __forceinline__ uint32_t packh2(float a, float b) {
    __half2 h = __floats2half2_rn(a, b);
    return *reinterpret_cast<uint32_t*>(&h);
}
__device__ __forceinline__ float2 unpackh2(uint32_t u) {
    __half2 h = *reinterpret_cast<__half2*>(&u);
    return __half22float2(h);
}
__device__ __forceinline__ uint32_t h2exp2(uint32_t x) {
    uint32_t d;
    asm("ex2.approx.f16x2 %0, %1;" : "=r"(d) : "r"(x));
    return d;
}

__device__ __forceinline__ void hmma(float* c, const uint32_t* a, uint32_t b0, uint32_t b1) {
    asm volatile(
        "mma.sync.aligned.m16n8k16.row.col.f32.f16.f16.f32 "
        "{%0,%1,%2,%3},{%4,%5,%6,%7},{%8,%9},{%0,%1,%2,%3};"
        : "+f"(c[0]), "+f"(c[1]), "+f"(c[2]), "+f"(c[3])
        : "r"(a[0]), "r"(a[1]), "r"(a[2]), "r"(a[3]), "r"(b0), "r"(b1));
}

__device__ __forceinline__ void ldsm4(uint32_t* r, uint32_t addr) {
    asm volatile("ldmatrix.sync.aligned.m8n8.x4.shared.b16 {%0,%1,%2,%3}, [%4];"
                 : "=r"(r[0]), "=r"(r[1]), "=r"(r[2]), "=r"(r[3]) : "r"(addr));
}
__device__ __forceinline__ void ldsm4t(uint32_t& r0, uint32_t& r1, uint32_t& r2, uint32_t& r3,
                                       uint32_t addr) {
    asm volatile("ldmatrix.sync.aligned.m8n8.x4.trans.shared.b16 {%0,%1,%2,%3}, [%4];"
                 : "=r"(r0), "=r"(r1), "=r"(r2), "=r"(r3) : "r"(addr));
}

__device__ __forceinline__ void cp16(uint32_t saddr, const void* gaddr) {
    asm volatile("cp.async.cg.shared.global [%0], [%1], 16;" :: "r"(saddr), "l"(gaddr));
}
__device__ __forceinline__ void cp_commit() {
    asm volatile("cp.async.commit_group;");
}
template <int N>
__device__ __forceinline__ void cp_wait() {
    asm volatile("cp.async.wait_group %0;" :: "n"(N));
}

__device__ __forceinline__ uint32_t ld32h(const __half* p) {
    return *reinterpret_cast<const uint32_t*>(p);
}

constexpr uint32_t ONES_H2 = 0x3C003C00u;  // (1.0h, 1.0h)

// ---------------------------------------------------------------------------
// Single fp32 -> fp16 conversion kernel: x + 4 weight matrices, one launch.
// ---------------------------------------------------------------------------
__global__ void tohalf_all(const float4* __restrict__ x,
                           const float4* __restrict__ w0, const float4* __restrict__ w1,
                           const float4* __restrict__ w2, const float4* __restrict__ w3,
                           uint2* __restrict__ xh, uint2* __restrict__ wh,
                           int nx4, int nw4)
{
    int i = blockIdx.x * blockDim.x + threadIdx.x;
    if (i < nx4) {
        float4 v = x[i];
        xh[i] = make_uint2(packh2(v.x, v.y), packh2(v.z, v.w));
    }
    int j = i - nx4;
    if (j >= 0 && j < 4 * nw4) {
        int seg = j / nw4;
        int off = j - seg * nw4;
        const float4* src = (seg == 0) ? w0 : (seg == 1) ? w1 : (seg == 2) ? w2 : w3;
        float4 v = src[off];
        wh[j] = make_uint2(packh2(v.x, v.y), packh2(v.z, v.w));
    }
}

// ---------------------------------------------------------------------------
// fp16 NT GEMM with ldmatrix fragments (R14/R16 version: issue AFTER compute).
// MODE 0: merged QKV projection (Q scaled by 0.125*log2e for exp2 domain).
// MODE 1: output projection (fp32 out).
// ---------------------------------------------------------------------------
template <int MODE>
__global__ __launch_bounds__(256, 2) void proj2(
    const __half* __restrict__ A, const __half* __restrict__ Bm,
    const float* __restrict__ b0, const float* __restrict__ b1,
    const float* __restrict__ b2, __half* __restrict__ outh,
    float* __restrict__ outf)
{
    constexpr int LD = 40;
    constexpr int AW = 128 * LD;
    constexpr int STAGE = 2 * AW;
    constexpr int NS = 4;
    extern __shared__ __half smh[];

    const int tid = threadIdx.x;
    const size_t bm = (size_t)blockIdx.y * 128;
    const size_t bn = (size_t)blockIdx.x * 128;
    constexpr int T = D_ / 32;

    auto issue = [&](int t, int s) {
        const int k0 = t * 32;
        __half* As = smh + s * STAGE;
        __half* Bs = As + AW;
#pragma unroll
        for (int i = 0; i < 2; i++) {
            int f = tid + 256 * i;
            int r = f >> 2;
            int c = (f & 3) * 8;
            cp16((uint32_t)__cvta_generic_to_shared(As + r * LD + c),
                 A + (bm + r) * (size_t)D_ + k0 + c);
            cp16((uint32_t)__cvta_generic_to_shared(Bs + r * LD + c),
                 Bm + (bn + r) * (size_t)D_ + k0 + c);
        }
    };

#pragma unroll
    for (int s = 0; s < NS - 1; s++) {
        issue(s, s);
        cp_commit();
    }

    const int warp = tid >> 5, lane = tid & 31;
    const int wm = (warp >> 1) * 32;
    const int wn = (warp & 1) * 64;
    const int grp = lane >> 2, qid = lane & 3;
    const int lr8 = lane & 7;
    const int am = (lane >> 3) & 1;
    const int ak = (lane >> 4) * 8;

    float acc[2][8][4];
#pragma unroll
    for (int i = 0; i < 2; i++)
#pragma unroll
        for (int j = 0; j < 8; j++)
#pragma unroll
            for (int r = 0; r < 4; r++) acc[i][j][r] = 0.f;

    for (int t = 0; t < T; t++) {
        cp_wait<NS - 2>();
        __syncthreads();
        const __half* As = smh + (t % NS) * STAGE;
        const __half* Bs = As + AW;

        uint32_t afr[2][2][4];
#pragma unroll
        for (int i = 0; i < 2; i++)
#pragma unroll
            for (int ks = 0; ks < 2; ks++)
                ldsm4(afr[i][ks],
                      (uint32_t)__cvta_generic_to_shared(
                          As + (wm + 16 * i + lr8 + am * 8) * LD + 16 * ks + ak));
#pragma unroll
        for (int j = 0; j < 8; j++) {
            uint32_t bfr[4];
            ldsm4(bfr, (uint32_t)__cvta_generic_to_shared(
                           Bs + (wn + 8 * j + lr8) * LD + (lane >> 3) * 8));
#pragma unroll
            for (int i = 0; i < 2; i++) {
                hmma(acc[i][j], afr[i][0], bfr[0], bfr[1]);
                hmma(acc[i][j], afr[i][1], bfr[2], bfr[3]);
            }
        }

        if (t + NS - 1 < T) issue(t + NS - 1, (t + NS - 1) % NS);
        cp_commit();
    }

    int seg = 0;
    const float* bias = b0;
    float alpha = 1.f;
    size_t ncolbase = bn;
    if (MODE == 0) {
        seg = blockIdx.x >> 3;
        bias = (seg == 0) ? b0 : (seg == 1) ? b1 : b2;
        alpha = (seg == 0) ? 0.18033688011116027f : 1.f;  // 0.125*log2(e)
        ncolbase = bn - (size_t)seg * 1024;
    }

#pragma unroll
    for (int i = 0; i < 2; i++) {
#pragma unroll
        for (int j = 0; j < 8; j++) {
            size_t row = bm + wm + 16 * i + grp;
            size_t col = ncolbase + wn + 8 * j + 2 * qid;
            float bx = bias[col], by = bias[col + 1];
            float v0 = (acc[i][j][0] + bx) * alpha;
            float v1 = (acc[i][j][1] + by) * alpha;
            float v2 = (acc[i][j][2] + bx) * alpha;
            float v3 = (acc[i][j][3] + by) * alpha;
            if (MODE == 0) {
                __half* C = outh + (size_t)seg * BSD;
                *(uint32_t*)(C + row * (size_t)D_ + col) = packh2(v0, v1);
                *(uint32_t*)(C + (row + 8) * (size_t)D_ + col) = packh2(v2, v3);
            } else {
                *(float2*)(outf + row * (size_t)D_ + col) = make_float2(v0, v1);
                *(float2*)(outf + (row + 8) * (size_t)D_ + col) = make_float2(v2, v3);
            }
        }
    }
}

// ---------------------------------------------------------------------------
// Fused fp16 attention.
// Pass A (NEW): each warp owns 32 q-rows x HALF the keys (key-split across
// warp halves). K fragments shared by 2 i-blocks -> ldsm per tile halved.
// Partial rowsums combined through a small smem table.
// Pass B: unchanged from R16 (verified 347.8 config).
// ---------------------------------------------------------------------------
constexpr int LDK2 = 72;                 // halves (64 + 8 pad) = 144B stride
constexpr int KW = 128 * LDK2;           // 9216 halves per 128-key tile
constexpr int CW = 2 * KW;               // K+V combined stage (pass B)
constexpr int SM_ATT_BYTES = 3 * CW * 2; // 110592 B
constexpr int KTA = 256;                 // pass-A keys per tile
constexpr int NTA = S_ / KTA;            // 8
constexpr int AW2 = KTA * LDK2;          // 18432 halves per stage
constexpr int KT = 128;                  // pass-B keys per tile
constexpr int NT_TILES = S_ / KT;        // 16

__global__ __launch_bounds__(256, 2) void attn_h(
    const __half* __restrict__ Q, const __half* __restrict__ K,
    const __half* __restrict__ V, float* __restrict__ attn,
    __half* __restrict__ ctx)
{
    extern __shared__ __half smh[];
    __half* sT = smh;

    const int tid = threadIdx.x;
    const int warp = tid >> 5, lane = tid & 31;
    const int grp = lane >> 2, qid = lane & 3;
    const int wm = warp * 16;

    const int z = blockIdx.y;
    const int b = z >> 4, h = z & 15;
    const size_t rowbase = (size_t)blockIdx.x * 128;
    const __half* Qg = Q + (size_t)b * S_ * D_ + h * HD_ + rowbase * D_;
    const __half* Kg = K + (size_t)b * S_ * D_ + h * HD_;
    const __half* Vg = V + (size_t)b * S_ * D_ + h * HD_;
    float* attng = attn + (size_t)z * S_ * S_ + rowbase * S_;

    auto issueKA = [&](int t, int s) {
        __half* kd = sT + s * AW2;
        const __half* src = Kg + (size_t)t * KTA * D_;
#pragma unroll
        for (int i = 0; i < 8; i++) {
            int f = tid + 256 * i;
            int r = f >> 3;
            int c = (f & 7) * 8;
            cp16((uint32_t)__cvta_generic_to_shared(kd + r * LDK2 + c),
                 src + (size_t)r * D_ + c);
        }
    };
    auto issueK = [&](int t, int s) {
        __half* kd = sT + s * CW;
        const __half* src = Kg + (size_t)t * KT * D_;
#pragma unroll
        for (int i = 0; i < 4; i++) {
            int f = tid + 256 * i;
            int r = f >> 3;
            int c = (f & 7) * 8;
            cp16((uint32_t)__cvta_generic_to_shared(kd + r * LDK2 + c),
                 src + (size_t)r * D_ + c);
        }
    };
    auto issueV = [&](int t, int s) {
        __half* vd = sT + s * CW + KW;
        const __half* src = Vg + (size_t)t * KT * D_;
#pragma unroll
        for (int i = 0; i < 4; i++) {
            int f = tid + 256 * i;
            int r = f >> 3;
            int c = (f & 7) * 8;
            cp16((uint32_t)__cvta_generic_to_shared(vd + r * LDK2 + c),
                 src + (size_t)r * D_ + c);
        }
    };

    // ================= Pass A: 32 rows/warp x half keys =================
    // warp w: rows (w&3)*32 .. +32 (2 i-blocks), keys (w>>2)*128 within tile
    {
        const int wmA = (warp & 3) * 32;
        const int khalf = (warp >> 2) * 128;

        uint32_t qaA[2][4][4];
#pragma unroll
        for (int i = 0; i < 2; i++) {
            const __half* q0 = Qg + (size_t)(wmA + 16 * i + grp) * D_;
            const __half* q1 = Qg + (size_t)(wmA + 16 * i + grp + 8) * D_;
#pragma unroll
            for (int ks = 0; ks < 4; ks++) {
                qaA[i][ks][0] = ld32h(q0 + 16 * ks + 2 * qid);
                qaA[i][ks][1] = ld32h(q1 + 16 * ks + 2 * qid);
                qaA[i][ks][2] = ld32h(q0 + 16 * ks + 2 * qid + 8);
                qaA[i][ks][3] = ld32h(q1 + 16 * ks + 2 * qid + 8);
            }
        }

        float rsA[2][4];
#pragma unroll
        for (int i = 0; i < 2; i++)
#pragma unroll
            for (int r = 0; r < 4; r++) rsA[i][r] = 0.f;

        issueKA(0, 0); cp_commit();
        issueKA(1, 1); cp_commit();
        for (int t = 0; t < NTA; t++) {
            cp_wait<1>();
            __syncthreads();
            const __half* Ks = sT + (t % 3) * AW2;
#pragma unroll
            for (int jjp = 0; jjp < 8; jjp++) {
                uint32_t pa0[4], pa1[4];
#pragma unroll
                for (int hx = 0; hx < 2; hx++) {
                    const int key8 = khalf + (2 * jjp + hx) * 8 + (lane & 7);
                    const __half* kp = Ks + key8 * LDK2 + ((lane >> 3) * 8);
                    uint32_t m[4];
                    float c0[4] = {0.f, 0.f, 0.f, 0.f};
                    float c1[4] = {0.f, 0.f, 0.f, 0.f};
                    ldsm4(m, (uint32_t)__cvta_generic_to_shared(kp));
                    hmma(c0, qaA[0][0], m[0], m[1]);
                    hmma(c0, qaA[0][1], m[2], m[3]);
                    hmma(c1, qaA[1][0], m[0], m[1]);
                    hmma(c1, qaA[1][1], m[2], m[3]);
                    ldsm4(m, (uint32_t)__cvta_generic_to_shared(kp + 32));
                    hmma(c0, qaA[0][2], m[0], m[1]);
                    hmma(c0, qaA[0][3], m[2], m[3]);
                    hmma(c1, qaA[1][2], m[0], m[1]);
                    hmma(c1, qaA[1][3], m[2], m[3]);
                    pa0[2 * hx + 0] = h2exp2(packh2(c0[0], c0[1]));
                    pa0[2 * hx + 1] = h2exp2(packh2(c0[2], c0[3]));
                    pa1[2 * hx + 0] = h2exp2(packh2(c1[0], c1[1]));
                    pa1[2 * hx + 1] = h2exp2(packh2(c1[2], c1[3]));
                }
                hmma(rsA[0], pa0, ONES_H2, ONES_H2);
                hmma(rsA[1], pa1, ONES_H2, ONES_H2);
            }
            if (t + 2 < NTA) issueKA(t + 2, (t + 2) % 3);
            cp_commit();
        }
        cp_wait<0>();
        __syncthreads();

        // combine partial rowsums through smem (reuse stage area)
        float* sRed = (float*)sT;  // 128 rows x 2 halves
        const int half = warp >> 2;
        if (qid == 0) {
#pragma unroll
            for (int i = 0; i < 2; i++) {
                sRed[(wmA + 16 * i + grp) * 2 + half] = rsA[i][0];
                sRed[(wmA + 16 * i + grp + 8) * 2 + half] = rsA[i][2];
            }
        }
        __syncthreads();
    }

    float* sRed = (float*)sT;
    const float rinv0 = 1.f / (sRed[(wm + grp) * 2] + sRed[(wm + grp) * 2 + 1]);
    const float rinv1 = 1.f / (sRed[(wm + grp + 8) * 2] + sRed[(wm + grp + 8) * 2 + 1]);
    __syncthreads();

    // pass-B Q fragments (warp's own 16 rows)
    uint32_t qa[4][4];
    {
        const __half* q0 = Qg + (size_t)(wm + grp) * D_;
        const __half* q1 = Qg + (size_t)(wm + grp + 8) * D_;
#pragma unroll
        for (int ks = 0; ks < 4; ks++) {
            qa[ks][0] = ld32h(q0 + 16 * ks + 2 * qid);
            qa[ks][1] = ld32h(q1 + 16 * ks + 2 * qid);
            qa[ks][2] = ld32h(q0 + 16 * ks + 2 * qid + 8);
            qa[ks][3] = ld32h(q1 + 16 * ks + 2 * qid + 8);
        }
    }

    auto smma = [&](const __half* Ks, int jj, float* c) {
        c[0] = c[1] = c[2] = c[3] = 0.f;
        const __half* kp = Ks + (jj * 8 + (lane & 7)) * LDK2 + ((lane >> 3) * 8);
        uint32_t m[4];
        ldsm4(m, (uint32_t)__cvta_generic_to_shared(kp));
        hmma(c, qa[0], m[0], m[1]);
        hmma(c, qa[1], m[2], m[3]);
        ldsm4(m, (uint32_t)__cvta_generic_to_shared(kp + 32));
        hmma(c, qa[2], m[0], m[1]);
        hmma(c, qa[3], m[2], m[3]);
    };

    // ================= Pass B: PV mma first, attn stores after ==============
    float cacc[8][4];
#pragma unroll
    for (int t = 0; t < 8; t++)
#pragma unroll
        for (int r = 0; r < 4; r++) cacc[t][r] = 0.f;

    issueK(0, 0); issueV(0, 0); cp_commit();
    issueK(1, 1); issueV(1, 1); cp_commit();

    const int sbl = (lane & ~3) + 2 * (qid & 1);
    const bool hiHalf = (qid >= 2);

    for (int t = 0; t < NT_TILES; t++) {
        cp_wait<1>();
        __syncthreads();
        const __half* Ks = sT + (t % 3) * CW;
        const __half* Vs = Ks + KW;

#pragma unroll
        for (int jjp = 0; jjp < 8; jjp++) {
            uint32_t pa[4];
#pragma unroll
            for (int hx = 0; hx < 2; hx++) {
                float c[4];
                smma(Ks, 2 * jjp + hx, c);
                pa[2 * hx + 0] = h2exp2(packh2(c[0], c[1]));  // row0 pair
                pa[2 * hx + 1] = h2exp2(packh2(c[2], c[3]));  // row1 pair
            }

            // PV first (keeps tensor pipe busy; stores depend only on pa)
            const int m = lane >> 3;
            const int keyr = 16 * jjp + (m & 1) * 8 + (lane & 7);
            const int dimo = (m >> 1) * 8;
#pragma unroll
            for (int nb = 0; nb < 4; nb++) {
                const __half* vp = Vs + keyr * LDK2 + nb * 16 + dimo;
                uint32_t r0, r1, r2, r3;
                ldsm4t(r0, r1, r2, r3, (uint32_t)__cvta_generic_to_shared(vp));
                hmma(cacc[2 * nb + 0], pa, r0, r1);
                hmma(cacc[2 * nb + 1], pa, r2, r3);
            }

            // attn stores: quad-shuffle regroup -> float4 per row
            {
                uint32_t a0 = __shfl_sync(0xffffffffu, pa[0], sbl);
                uint32_t a1 = __shfl_sync(0xffffffffu, pa[0], sbl + 1);
                uint32_t b0 = __shfl_sync(0xffffffffu, pa[2], sbl);
                uint32_t b1 = __shfl_sync(0xffffffffu, pa[2], sbl + 1);
                uint32_t u0 = hiHalf ? b0 : a0;
                uint32_t u1 = hiHalf ? b1 : a1;
                float2 f0 = unpackh2(u0), f1 = unpackh2(u1);
                const size_t col = (size_t)t * KT + jjp * 16 + 4 * qid;
                float4 o;
                o.x = f0.x * rinv0; o.y = f0.y * rinv0;
                o.z = f1.x * rinv0; o.w = f1.y * rinv0;
                __stcs((float4*)(attng + (size_t)(wm + grp) * S_ + col), o);

                a0 = __shfl_sync(0xffffffffu, pa[1], sbl);
                a1 = __shfl_sync(0xffffffffu, pa[1], sbl + 1);
                b0 = __shfl_sync(0xffffffffu, pa[3], sbl);
                b1 = __shfl_sync(0xffffffffu, pa[3], sbl + 1);
                u0 = hiHalf ? b0 : a0;
                u1 = hiHalf ? b1 : a1;
                f0 = unpackh2(u0); f1 = unpackh2(u1);
                o.x = f0.x * rinv1; o.y = f0.y * rinv1;
                o.z = f1.x * rinv1; o.w = f1.y * rinv1;
                __stcs((float4*)(attng + (size_t)(wm + grp + 8) * S_ + col), o);
            }
        }
        if (t + 2 < NT_TILES) { issueK(t + 2, (t + 2) % 3); issueV(t + 2, (t + 2) % 3); }
        cp_commit();
    }

    __half* ctxg = ctx + (size_t)b * S_ * D_ + h * HD_ + rowbase * D_;
#pragma unroll
    for (int tt = 0; tt < 8; tt++) {
        const int col = 8 * tt + 2 * qid;
        *(uint32_t*)(ctxg + (size_t)(wm + grp) * D_ + col) =
            packh2(cacc[tt][0] * rinv0, cacc[tt][1] * rinv0);
        *(uint32_t*)(ctxg + (size_t)(wm + grp + 8) * D_ + col) =
            packh2(cacc[tt][2] * rinv1, cacc[tt][3] * rinv1);
    }
}

// ---------------------------------------------------------------------------
extern "C" void kernel_launch(void* const* d_in, const int* in_sizes, int n_in,
                              void* d_out, int out_size)
{
    const float* x  = (const float*)d_in[0];
    const float* Wq = (const float*)d_in[1];
    const float* bq = (const float*)d_in[2];
    const float* Wk = (const float*)d_in[3];
    const float* bk = (const float*)d_in[4];
    const float* Wv = (const float*)d_in[5];
    const float* bv = (const float*)d_in[6];
    const float* Wo = (const float*)d_in[7];
    const float* bo = (const float*)d_in[8];

    float* out = (float*)d_out;

    __half *QKV, *Cp, *Xp, *Wh;
    cudaGetSymbolAddress((void**)&QKV, g_QKVh);
    cudaGetSymbolAddress((void**)&Cp, g_Ch);
    cudaGetSymbolAddress((void**)&Xp, g_Xh);
    cudaGetSymbolAddress((void**)&Wh, g_Wh);

    float* attn;
    if ((size_t)out_size >= BSD + BHSS) {
        attn = out + BSD;
    } else {
        cudaGetSymbolAddress((void**)&attn, g_attn_fallback);
    }

    constexpr int WN = D_ * D_;
    constexpr int W4 = WN / 4;        // float4 per weight matrix
    constexpr int X4 = (int)(BSD / 4);

    // 0) convert x + all 4 weights in ONE launch
    tohalf_all<<<(X4 + 4 * W4 + 255) / 256, 256>>>(
        (const float4*)x, (const float4*)Wq, (const float4*)Wk,
        (const float4*)Wv, (const float4*)Wo,
        (uint2*)Xp, (uint2*)Wh, X4, W4);

    constexpr int SMEM_P = 4 * (2 * 128 * 40) * 2;  // 81920 B
    cudaFuncSetAttribute(proj2<0>, cudaFuncAttributeMaxDynamicSharedMemorySize, SMEM_P);
    cudaFuncSetAttribute(proj2<1>, cudaFuncAttributeMaxDynamicSharedMemorySize, SMEM_P);
    cudaFuncSetAttribute(attn_h, cudaFuncAttributeMaxDynamicSharedMemorySize, SM_ATT_BYTES);

    // 1) merged QKV projection (Q in exp2 domain)
    dim3 gqkv(3 * D_ / 128, (B_ * S_) / 128);  // (24, 32)
    proj2<0><<<gqkv, 256, SMEM_P>>>(Xp, Wh, bq, bk, bv, QKV, nullptr);

    // 2) fused attention (pass A: 32 rows/warp x half keys)
    dim3 gatt(S_ / 128, B_ * H_);  // (16, 32)
    attn_h<<<gatt, 256, SM_ATT_BYTES>>>(QKV, QKV + BSD, QKV + 2 * BSD, attn, Cp);

    // 3) out = ctx @ Wo^T + bo (fp32 output)
    dim3 gout(D_ / 128, (B_ * S_) / 128);  // (8, 32)
    proj2<1><<<gout, 256, SMEM_P>>>(Cp, Wh + 3 * WN, bo, nullptr, nullptr, nullptr, out);
}